// round 16
// baseline (speedup 1.0000x reference)
#include <cuda_runtime.h>
#include <cuda_bf16.h>
#include <mma.h>
#include <math.h>

using namespace nvcuda;

#define BB 16
#define NN 512
#define CC 512
#define NS 16
#define CM 64           // CC / S
#define ROWS (BB*NN)    // 8192

typedef unsigned long long ull;

__device__ __forceinline__ void ffma2(ull &d, ull a, ull b) {
    asm("fma.rn.f32x2 %0, %1, %2, %0;" : "+l"(d) : "l"(a), "l"(b));
}
__device__ __forceinline__ ull pack2(float lo, float hi) {
    ull r; asm("mov.b64 %0, {%1, %2};" : "=l"(r) : "f"(lo), "f"(hi)); return r;
}
__device__ __forceinline__ void unpack2(float &lo, float &hi, ull v) {
    asm("mov.b64 {%0, %1}, %2;" : "=f"(lo), "=f"(hi) : "l"(v));
}
__device__ __forceinline__ unsigned bf16pair(float a, float b,
                                             float &la, float &lb) {
    __nv_bfloat16 h0 = __float2bfloat16(a);
    __nv_bfloat16 h1 = __float2bfloat16(b);
    la = a - __bfloat162float(h0);
    lb = b - __bfloat162float(h1);
    __nv_bfloat162 hp = __halves2bfloat162(h0, h1);
    return *reinterpret_cast<unsigned*>(&hp);
}

// ---------------- scratch (static device globals; no allocation) -------------
__device__ float g_xq[ROWS*CC];
__device__ float g_xk[ROWS*CC];
__device__ float g_xv[ROWS*CC];
__device__ int   g_idx[ROWS*NS];

// ================= stage1: WMMA bf16-split QKV GEMM + kNN ====================
// Blocks [0,768): qkv 128x128 tiles (z = bid>>8). Blocks [768,1792): kNN.
// smem bytes: [0,8192) bias tile 16x128 f32 (knn reuses as ps/sq)
//   [8192,25600) Ahi bf16[64][136]; [25600,43008) Alo
//   [43008,60416) Bhi bf16[64][136]; [60416,77824) Blo
#define QKV_BLOCKS 768
#define S1_AHI 8192
#define S1_ALO 25600
#define S1_BHI 43008
#define S1_BLO 60416
#define S1_TOT 77824
#define LDMB 136

__global__ __launch_bounds__(256) void stage1_kernel(
    const float* __restrict__ p,
    const float* __restrict__ x,
    const float* __restrict__ Wq, const float* __restrict__ bq,
    const float* __restrict__ Wk, const float* __restrict__ bk,
    const float* __restrict__ Wv, const float* __restrict__ bv)
{
    extern __shared__ __align__(16) char smc[];
    const int tid = threadIdx.x;

    if (blockIdx.x < QKV_BLOCKS) {
        float* biasT = reinterpret_cast<float*>(smc);
        __nv_bfloat16* Ahi = reinterpret_cast<__nv_bfloat16*>(smc + S1_AHI);
        __nv_bfloat16* Alo = reinterpret_cast<__nv_bfloat16*>(smc + S1_ALO);
        __nv_bfloat16* Bhi = reinterpret_cast<__nv_bfloat16*>(smc + S1_BHI);
        __nv_bfloat16* Blo = reinterpret_cast<__nv_bfloat16*>(smc + S1_BLO);

        const int z    = blockIdx.x >> 8;
        const int tile = blockIdx.x & 255;
        const float* W; const float* bias; float* out;
        if (z == 0)      { W = Wq; bias = bq; out = g_xq; }
        else if (z == 1) { W = Wk; bias = bk; out = g_xk; }
        else             { W = Wv; bias = bv; out = g_xv; }

        const int m0 = (tile >> 2) * 128;   // row tile (point dim)
        const int c0 = (tile & 3) * 128;    // col tile
        const int b  = m0 >> 9;
        const int n0 = m0 & 511;
        const float* xb = x + (size_t)b * CC * NN;
        const int wid = tid >> 5;

        // bias tile: 16 identical rows of bias[c0..c0+127]
        for (int i = tid; i < 16*128; i += 256)
            biasT[i] = bias[c0 + (i & 127)];
        __syncthreads();

        wmma::fragment<wmma::accumulator, 16, 16, 16, float> acc[8];
#pragma unroll
        for (int nt = 0; nt < 8; nt++)
            wmma::load_matrix_sync(acc[nt], biasT + nt*16, 128,
                                   wmma::mem_row_major);

#pragma unroll 1
        for (int kc = 0; kc < 8; kc++) {
            const int k0 = kc * 64;
            // stage A (x) and B (W): 2048 float4 each, 8 per thread each
#pragma unroll
            for (int it = 0; it < 8; it++) {
                int t = tid + it*256;
                int k = t >> 5;
                int n4 = (t & 31) * 4;
                float4 v = *reinterpret_cast<const float4*>(
                    &xb[(size_t)(k0+k)*NN + n0 + n4]);
                float l0, l1, l2, l3;
                unsigned h01 = bf16pair(v.x, v.y, l0, l1);
                unsigned h23 = bf16pair(v.z, v.w, l2, l3);
                __nv_bfloat162 lp01 = __floats2bfloat162_rn(l0, l1);
                __nv_bfloat162 lp23 = __floats2bfloat162_rn(l2, l3);
                unsigned* dh = reinterpret_cast<unsigned*>(&Ahi[k*LDMB + n4]);
                unsigned* dl = reinterpret_cast<unsigned*>(&Alo[k*LDMB + n4]);
                dh[0] = h01; dh[1] = h23;
                dl[0] = *reinterpret_cast<unsigned*>(&lp01);
                dl[1] = *reinterpret_cast<unsigned*>(&lp23);
            }
#pragma unroll
            for (int it = 0; it < 8; it++) {
                int t = tid + it*256;
                int k = t >> 5;
                int c4 = (t & 31) * 4;
                float4 v = *reinterpret_cast<const float4*>(
                    &W[(size_t)(k0+k)*CC + c0 + c4]);
                float l0, l1, l2, l3;
                unsigned h01 = bf16pair(v.x, v.y, l0, l1);
                unsigned h23 = bf16pair(v.z, v.w, l2, l3);
                __nv_bfloat162 lp01 = __floats2bfloat162_rn(l0, l1);
                __nv_bfloat162 lp23 = __floats2bfloat162_rn(l2, l3);
                unsigned* dh = reinterpret_cast<unsigned*>(&Bhi[k*LDMB + c4]);
                unsigned* dl = reinterpret_cast<unsigned*>(&Blo[k*LDMB + c4]);
                dh[0] = h01; dh[1] = h23;
                dl[0] = *reinterpret_cast<unsigned*>(&lp01);
                dl[1] = *reinterpret_cast<unsigned*>(&lp23);
            }
            __syncthreads();

            // MMA: warp wid owns rows [wid*16, wid*16+16)
#pragma unroll
            for (int ks = 0; ks < 4; ks++) {
                wmma::fragment<wmma::matrix_a, 16, 16, 16, __nv_bfloat16,
                               wmma::col_major> a_hi, a_lo;
                wmma::load_matrix_sync(a_hi, Ahi + (ks*16)*LDMB + wid*16, LDMB);
                wmma::load_matrix_sync(a_lo, Alo + (ks*16)*LDMB + wid*16, LDMB);
#pragma unroll
                for (int nt = 0; nt < 8; nt++) {
                    wmma::fragment<wmma::matrix_b, 16, 16, 16, __nv_bfloat16,
                                   wmma::row_major> b_hi, b_lo;
                    wmma::load_matrix_sync(b_hi, Bhi + (ks*16)*LDMB + nt*16, LDMB);
                    wmma::load_matrix_sync(b_lo, Blo + (ks*16)*LDMB + nt*16, LDMB);
                    wmma::mma_sync(acc[nt], a_hi, b_hi, acc[nt]);
                    wmma::mma_sync(acc[nt], a_hi, b_lo, acc[nt]);
                    wmma::mma_sync(acc[nt], a_lo, b_hi, acc[nt]);
                }
            }
            __syncthreads();
        }

        const int row = m0 + wid*16;
#pragma unroll
        for (int nt = 0; nt < 8; nt++)
            wmma::store_matrix_sync(&out[(size_t)row*CC + c0 + nt*16],
                                    acc[nt], CC, wmma::mem_row_major);
    } else {
        // kNN: warp per query; ulp-exact distances
        float* ps = reinterpret_cast<float*>(smc);
        float* sq = ps + NN*3;
        const int kb   = blockIdx.x - QKV_BLOCKS;
        const int b    = kb >> 6;
        const int warp = tid >> 5;
        const int lane = tid & 31;
        const float* pb = p + (size_t)b * NN * 3;
        for (int i = tid; i < NN*3; i += 256) ps[i] = pb[i];
        __syncthreads();
        for (int i = tid; i < NN; i += 256) {
            float m0 = __fmul_rn(ps[i*3+0], ps[i*3+0]);
            float m1 = __fmul_rn(ps[i*3+1], ps[i*3+1]);
            float m2 = __fmul_rn(ps[i*3+2], ps[i*3+2]);
            sq[i] = __fadd_rn(__fadd_rn(m0, m1), m2);
        }
        __syncthreads();

        const int n = (kb & 63) * 8 + warp;
        const float px = ps[n*3+0], py = ps[n*3+1], pz = ps[n*3+2];
        const float sn = sq[n];

        float d[16];
#pragma unroll
        for (int i = 0; i < 16; i++) {
            int m = lane * 16 + i;
            float dot = __fmul_rn(px, ps[m*3+0]);
            dot = fmaf(py, ps[m*3+1], dot);
            dot = fmaf(pz, ps[m*3+2], dot);
            d[i] = __fsub_rn(__fadd_rn(sn, sq[m]), __fmul_rn(2.0f, dot));
        }

        const int row = b*NN + n;
        const float INF = __int_as_float(0x7f800000);
#pragma unroll 1
        for (int t = 0; t < NS; t++) {
            float bd = d[0]; int bi = 0;
#pragma unroll
            for (int i = 1; i < 16; i++) if (d[i] < bd) { bd = d[i]; bi = i; }
            int ib = __float_as_int(bd);
            unsigned u = (unsigned)ib ^ ((ib < 0) ? 0xFFFFFFFFu : 0x80000000u);
            ull key = ((ull)u << 32) | (unsigned)(lane*16 + bi);
#pragma unroll
            for (int s = 16; s > 0; s >>= 1) {
                ull o = __shfl_xor_sync(0xFFFFFFFFu, key, s);
                if (o < key) key = o;
            }
            int win_m = (int)(key & 0xFFFFFFFFu);
            if ((win_m >> 4) == lane) {
                int wi = win_m & 15;
#pragma unroll
                for (int i = 0; i < 16; i++) if (i == wi) d[i] = INF;
            }
            if (lane == 0) g_idx[row*NS + t] = win_m;
        }
    }
}

// ============================ main fused kernel ==============================
// (identical to round-14 passing version: 4 pts/block, ping-pong phase-B,
//  W1/W2 direct from global)
#define SM_AS   0
#define SM_PS   8448
#define SM_XQ   16896
#define SM_B1S  18944
#define SM_B1O  19456
#define SM_H    19968
#define SM_IDX  20160
#define SM_TOT  20224   // floats -> 80896 bytes

__global__ __launch_bounds__(256, 2) void pt_main(
    const float* __restrict__ p,
    const float* __restrict__ p1W,  const float* __restrict__ p1b,
    const float* __restrict__ pbng, const float* __restrict__ pbnb,
    const float* __restrict__ p2W,  const float* __restrict__ p2b,
    const float* __restrict__ bn1g, const float* __restrict__ bn1bv,
    const float* __restrict__ W1,   const float* __restrict__ b1,
    const float* __restrict__ bn2g, const float* __restrict__ bn2bv,
    const float* __restrict__ W2,   const float* __restrict__ b2,
    float* __restrict__ out)
{
    extern __shared__ __align__(16) float sm[];
    float* aS   = sm + SM_AS;
    float* pS   = sm + SM_PS;
    float* xqS  = sm + SM_XQ;
    float* b1sS = sm + SM_B1S;
    float* b1oS = sm + SM_B1O;
    float* hS   = sm + SM_H;
    int*   idxS = (int*)(sm + SM_IDX);

    const int tid  = threadIdx.x;
    const int row0 = blockIdx.x * 4;
    const int b    = row0 >> 9;
    const float RS = rsqrtf(1.0f + 1e-5f);

    if (tid < 64) {
        int pt = tid >> 4;
        int row = row0 + pt;
        int m = g_idx[row*NS + (tid & 15)];
        idxS[tid] = m;
        int gm = b*NN + m;
        float prx = p[gm*3+0] - p[row*3+0];
        float pry = p[gm*3+1] - p[row*3+1];
        float prz = p[gm*3+2] - p[row*3+2];
#pragma unroll
        for (int j = 0; j < 3; j++) {
            float v = prx*p1W[0*3+j] + pry*p1W[1*3+j] + prz*p1W[2*3+j] + p1b[j];
            v = v * (pbng[j] * RS) + pbnb[j];
            hS[tid*3+j] = fmaxf(v, 0.0f);
        }
    }
#pragma unroll
    for (int i = 0; i < 2; i++) {
        int s = tid + i*256;
        int pt = s >> 7, c4 = (s & 127) * 4;
        *reinterpret_cast<float4*>(&xqS[pt*512 + c4]) =
            *reinterpret_cast<const float4*>(&g_xq[(size_t)(row0+pt)*CC + c4]);
    }
#pragma unroll
    for (int i = 0; i < 2; i++) {
        int c = tid + i*256;
        b1sS[c] = bn1g[c] * RS;
        b1oS[c] = bn1bv[c];
    }
    __syncthreads();

    const int cg = tid & 7;
    const int jg = (tid >> 3) & 1;
    const int pt = (tid >> 4) & 3;
    const int ks = tid >> 6;

    auto phaseB = [&](int kc, float* buf) {
#pragma unroll
        for (int i = 0; i < 8; i++) {
            int s = tid + i*256;
            int r = s >> 5, k4 = (s & 31) * 4;
            int c = kc*128 + k4;
            int ptb = r >> 4;
            int m  = idxS[r];
            float h0 = hS[r*3+0], h1 = hS[r*3+1], h2 = hS[r*3+2];
            float4 xk4 = *reinterpret_cast<const float4*>(&g_xk[(size_t)(b*NN+m)*CC + c]);
            float4 q04 = *reinterpret_cast<const float4*>(&p2W[c]);
            float4 q14 = *reinterpret_cast<const float4*>(&p2W[CC + c]);
            float4 q24 = *reinterpret_cast<const float4*>(&p2W[2*CC + c]);
            float4 pb4 = *reinterpret_cast<const float4*>(&p2b[c]);
            float4 xq4 = *reinterpret_cast<const float4*>(&xqS[ptb*512 + c]);
            float4 s14 = *reinterpret_cast<const float4*>(&b1sS[c]);
            float4 o14 = *reinterpret_cast<const float4*>(&b1oS[c]);
            float4 res;
            {
                float pr = h0*q04.x + h1*q14.x + h2*q24.x + pb4.x;
                res.x = fmaxf(fmaf(xk4.x - xq4.x + pr, s14.x, o14.x), 0.0f);
                pr = h0*q04.y + h1*q14.y + h2*q24.y + pb4.y;
                res.y = fmaxf(fmaf(xk4.y - xq4.y + pr, s14.y, o14.y), 0.0f);
                pr = h0*q04.z + h1*q14.z + h2*q24.z + pb4.z;
                res.z = fmaxf(fmaf(xk4.z - xq4.z + pr, s14.z, o14.z), 0.0f);
                pr = h0*q04.w + h1*q14.w + h2*q24.w + pb4.w;
                res.w = fmaxf(fmaf(xk4.w - xq4.w + pr, s14.w, o14.w), 0.0f);
            }
            *reinterpret_cast<float4*>(&buf[r*132 + k4]) = res;
        }
    };

    ull acc[8][4];
#pragma unroll
    for (int j = 0; j < 8; j++)
#pragma unroll
        for (int cp = 0; cp < 4; cp++) acc[j][cp] = 0ULL;

    phaseB(0, aS);
    __syncthreads();

#pragma unroll 1
    for (int kc = 0; kc < 4; kc++) {
        float* cur = (kc & 1) ? pS : aS;
        float* nxt = (kc & 1) ? aS : pS;
        if (kc < 3) phaseB(kc+1, nxt);
        {
            const float* aB = cur + (pt*16 + jg*8)*132 + ks*32;
            const float* wB = W1 + (size_t)(kc*128 + ks*32)*CM + cg*8;
#pragma unroll 2
            for (int k4 = 0; k4 < 32; k4 += 4) {
                float4 av[8];
#pragma unroll
                for (int j = 0; j < 8; j++)
                    av[j] = *reinterpret_cast<const float4*>(aB + j*132 + k4);
#pragma unroll
                for (int kk = 0; kk < 4; kk++) {
                    const float* wrow = wB + (size_t)(k4+kk)*CM;
                    ulonglong2 w01 = *reinterpret_cast<const ulonglong2*>(wrow);
                    ulonglong2 w23 = *reinterpret_cast<const ulonglong2*>(wrow + 4);
#pragma unroll
                    for (int j = 0; j < 8; j++) {
                        const float* af = (const float*)&av[j];
                        float a = af[kk];
                        ull ad = pack2(a, a);
                        ffma2(acc[j][0], ad, w01.x);
                        ffma2(acc[j][1], ad, w01.y);
                        ffma2(acc[j][2], ad, w23.x);
                        ffma2(acc[j][3], ad, w23.y);
                    }
                }
            }
        }
        __syncthreads();
    }

    {
        float* dst = ((ks < 2) ? aS : pS) + (ks & 1) * 4096;
        int base = pt*1024 + jg*8*64 + cg*8;
#pragma unroll
        for (int j = 0; j < 8; j++) {
#pragma unroll
            for (int cp = 0; cp < 4; cp++) {
                float lo, hi;
                unpack2(lo, hi, acc[j][cp]);
                *reinterpret_cast<float2*>(&dst[base + j*64 + cp*2]) =
                    make_float2(lo, hi);
            }
        }
    }
    __syncthreads();

    float a2v[16];
#pragma unroll
    for (int i = 0; i < 16; i++) {
        int o = tid + i*256;
        int c = o & 63;
        float s = aS[o] + aS[4096 + o] + pS[o] + pS[4096 + o];
        s += b1[c];
        s = fmaf(s, bn2g[c]*RS, bn2bv[c]);
        a2v[i] = fmaxf(s, 0.0f);
    }
    __syncthreads();

#pragma unroll
    for (int i = 0; i < 16; i++) {
        int o = tid + i*256;
        int r = o >> 6, c = o & 63;
        aS[r*68 + c] = a2v[i];
    }
    __syncthreads();

    {
        const int cg2 = tid & 7;
        const int jg2 = (tid >> 3) & 1;
        const int pt2 = (tid >> 4) & 3;
        const int jh  = tid >> 7;
        ull acc2[4][4];
#pragma unroll
        for (int j = 0; j < 4; j++)
#pragma unroll
            for (int cp = 0; cp < 4; cp++) acc2[j][cp] = 0ULL;

        const float* aB = aS + (pt2*16 + jg2*8 + jh*4)*68;
        const float* wB = W2 + cg2*8;
#pragma unroll 2
        for (int k4 = 0; k4 < 64; k4 += 4) {
            float4 av[4];
#pragma unroll
            for (int j = 0; j < 4; j++)
                av[j] = *reinterpret_cast<const float4*>(aB + j*68 + k4);
#pragma unroll
            for (int kk = 0; kk < 4; kk++) {
                const float* wrow = wB + (size_t)(k4+kk)*CM;
                ulonglong2 w01 = *reinterpret_cast<const ulonglong2*>(wrow);
                ulonglong2 w23 = *reinterpret_cast<const ulonglong2*>(wrow + 4);
#pragma unroll
                for (int j = 0; j < 4; j++) {
                    const float* af = (const float*)&av[j];
                    float a = af[kk];
                    ull ad = pack2(a, a);
                    ffma2(acc2[j][0], ad, w01.x);
                    ffma2(acc2[j][1], ad, w01.y);
                    ffma2(acc2[j][2], ad, w23.x);
                    ffma2(acc2[j][3], ad, w23.y);
                }
            }
        }
        float* y2 = pS;
        int base = pt2*1024 + (jg2*8 + jh*4)*64 + cg2*8;
#pragma unroll
        for (int j = 0; j < 4; j++) {
#pragma unroll
            for (int cp = 0; cp < 4; cp++) {
                float lo, hi;
                unpack2(lo, hi, acc2[j][cp]);
                int c = cg2*8 + cp*2;
                *reinterpret_cast<float2*>(&y2[base + j*64 + cp*2]) =
                    make_float2(lo + b2[c], hi + b2[c+1]);
            }
        }
    }
    __syncthreads();

    {
        float* y2 = pS;
        int ptc = tid >> 6;
        int c   = tid & 63;
        float* col = y2 + ptc*1024 + c;
        float mx = -3.4e38f;
#pragma unroll
        for (int j = 0; j < NS; j++) mx = fmaxf(mx, col[j*64]);
        float ex[NS];
        float sum = 0.0f;
#pragma unroll
        for (int j = 0; j < NS; j++) {
            ex[j] = expf(col[j*64] - mx);
            sum += ex[j];
        }
        float inv = 1.0f / sum;
#pragma unroll
        for (int j = 0; j < NS; j++) col[j*64] = ex[j] * inv;
    }
    __syncthreads();

    {
        const float* y2 = pS;
#pragma unroll
        for (int i = 0; i < 2; i++) {
            int s = tid + i*256;
            int ptb = s >> 7;
            int cf  = (s & 127) * 4;
            int cc  = cf & 63;
            float4 q0 = *reinterpret_cast<const float4*>(&p2W[cf]);
            float4 q1 = *reinterpret_cast<const float4*>(&p2W[CC + cf]);
            float4 q2 = *reinterpret_cast<const float4*>(&p2W[2*CC + cf]);
            float4 qb = *reinterpret_cast<const float4*>(&p2b[cf]);
            const float* ybase = y2 + ptb*1024 + cc;
            const int* idxp = idxS + ptb*16;
            const float* hp = hS + ptb*48;
            float4 acco = make_float4(0.f, 0.f, 0.f, 0.f);
#pragma unroll
            for (int j = 0; j < NS; j++) {
                int m = idxp[j];
                float h0 = hp[j*3+0], h1 = hp[j*3+1], h2 = hp[j*3+2];
                float4 xv4 = *reinterpret_cast<const float4*>(&g_xv[(size_t)(b*NN+m)*CC + cf]);
                float4 w4  = *reinterpret_cast<const float4*>(ybase + j*64);
                float pr;
                pr = h0*q0.x + h1*q1.x + h2*q2.x + qb.x;
                acco.x = fmaf(xv4.x + pr, w4.x, acco.x);
                pr = h0*q0.y + h1*q1.y + h2*q2.y + qb.y;
                acco.y = fmaf(xv4.y + pr, w4.y, acco.y);
                pr = h0*q0.z + h1*q1.z + h2*q2.z + qb.z;
                acco.z = fmaf(xv4.z + pr, w4.z, acco.z);
                pr = h0*q0.w + h1*q1.w + h2*q2.w + qb.w;
                acco.w = fmaf(xv4.w + pr, w4.w, acco.w);
            }
            *reinterpret_cast<float4*>(&out[(size_t)(row0+ptb)*CC + cf]) = acco;
        }
    }
}

// ============================ launcher =======================================
extern "C" void kernel_launch(void* const* d_in, const int* in_sizes, int n_in,
                              void* d_out, int out_size)
{
    const float* p    = (const float*)d_in[0];
    const float* x    = (const float*)d_in[1];
    const float* Wq   = (const float*)d_in[2];
    const float* bq   = (const float*)d_in[3];
    const float* Wk   = (const float*)d_in[4];
    const float* bk   = (const float*)d_in[5];
    const float* Wv   = (const float*)d_in[6];
    const float* bv   = (const float*)d_in[7];
    const float* p1W  = (const float*)d_in[8];
    const float* p1b  = (const float*)d_in[9];
    const float* pbng = (const float*)d_in[10];
    const float* pbnb = (const float*)d_in[11];
    const float* p2W  = (const float*)d_in[12];
    const float* p2b  = (const float*)d_in[13];
    const float* bn1g = (const float*)d_in[14];
    const float* bn1b = (const float*)d_in[15];
    const float* W1   = (const float*)d_in[16];
    const float* b1   = (const float*)d_in[17];
    const float* bn2g = (const float*)d_in[18];
    const float* bn2b = (const float*)d_in[19];
    const float* W2   = (const float*)d_in[20];
    const float* b2   = (const float*)d_in[21];
    float* out = (float*)d_out;

    cudaFuncSetAttribute(stage1_kernel, cudaFuncAttributeMaxDynamicSharedMemorySize,
                         S1_TOT);
    cudaFuncSetAttribute(pt_main, cudaFuncAttributeMaxDynamicSharedMemorySize,
                         SM_TOT * sizeof(float));

    stage1_kernel<<<QKV_BLOCKS + BB*64, 256, S1_TOT>>>(p, x, Wq, bq, Wk, bk, Wv, bv);
    pt_main<<<ROWS/4, 256, SM_TOT * sizeof(float)>>>(
        p, p1W, p1b, pbng, pbnb, p2W, p2b,
        bn1g, bn1b, W1, b1, bn2g, bn2b, W2, b2, out);
}